// round 15
// baseline (speedup 1.0000x reference)
#include <cuda_runtime.h>
#include <math.h>

#define Bn 64
#define Sn 32
#define Vn 512
#define Wn 2048
#define N0 13   // half0: entry + layers 0..12 (rows); half1: layers 13..31 + exit (column)

typedef unsigned long long u64t;

// Scratch (no allocations allowed)
__device__ __align__(16) float g_q[Bn * Sn * 8];  // [b][s][m] material weight
__device__ float g_traw[Bn * Sn];                 // thickness before survival
__device__ float g_pe[Bn * Sn];                   // clipped eos prob

__device__ __forceinline__ float ldF(const void* p, int i, bool f64) {
    return f64 ? (float)((const double*)p)[i] : ((const float*)p)[i];
}

__device__ __forceinline__ int is_f64(const void* p, int start, float lo, float hi) {
    const float* f = (const float*)p;
    for (int i = 0; i < 16; ++i) {
        float v = f[start + 2 * i];
        if (!(v >= lo && v <= hi)) return 1;
    }
    return 0;
}

// ---- packed f32x2 helpers ----
__device__ __forceinline__ u64t pk(float lo, float hi) {
    u64t r; asm("mov.b64 %0, {%1,%2};" : "=l"(r) : "f"(lo), "f"(hi)); return r;
}
__device__ __forceinline__ u64t pks(float x) { return pk(x, x); }
__device__ __forceinline__ void upk(u64t a, float& lo, float& hi) {
    asm("mov.b64 {%0,%1}, %2;" : "=f"(lo), "=f"(hi) : "l"(a));
}
__device__ __forceinline__ u64t mul2(u64t a, u64t b) {
    u64t r; asm("mul.rn.f32x2 %0,%1,%2;" : "=l"(r) : "l"(a), "l"(b)); return r;
}
__device__ __forceinline__ u64t add2(u64t a, u64t b) {
    u64t r; asm("add.rn.f32x2 %0,%1,%2;" : "=l"(r) : "l"(a), "l"(b)); return r;
}
__device__ __forceinline__ u64t sub2(u64t a, u64t b) {
    u64t r; asm("sub.rn.f32x2 %0,%1,%2;" : "=l"(r) : "l"(a), "l"(b)); return r;
}
__device__ __forceinline__ u64t fma2(u64t a, u64t b, u64t c) {
    u64t r; asm("fma.rn.f32x2 %0,%1,%2,%3;" : "=l"(r) : "l"(a), "l"(b), "l"(c)); return r;
}
__device__ __forceinline__ u64t neg2(u64t a) { return a ^ 0x8000000080000000ULL; }

// Scalar-FADD pair versions: identical rounding to f32x2, but issue as two
// scalar add.rn.f32 -> second (alu) datapath, relieving the FMA pipe.
__device__ __forceinline__ u64t adds2(u64t a, u64t b) {
    u64t r;
    asm("{\n\t.reg .f32 al,ah,bl,bh,cl,ch;\n\t"
        "mov.b64 {al,ah}, %1;\n\t"
        "mov.b64 {bl,bh}, %2;\n\t"
        "add.rn.f32 cl, al, bl;\n\t"
        "add.rn.f32 ch, ah, bh;\n\t"
        "mov.b64 %0, {cl,ch};\n\t}"
        : "=l"(r) : "l"(a), "l"(b));
    return r;
}
__device__ __forceinline__ u64t subs2(u64t a, u64t b) {
    u64t r;
    asm("{\n\t.reg .f32 al,ah,bl,bh,cl,ch;\n\t"
        "mov.b64 {al,ah}, %1;\n\t"
        "mov.b64 {bl,bh}, %2;\n\t"
        "sub.rn.f32 cl, al, bl;\n\t"
        "sub.rn.f32 ch, ah, bh;\n\t"
        "mov.b64 %0, {cl,ch};\n\t}"
        : "=l"(r) : "l"(a), "l"(b));
    return r;
}

// ---------------------------------------------------------------------------
// Kernel 1: prep. grid = Bn*4 blocks, 256 threads; ONE WARP per (b,s).
// ---------------------------------------------------------------------------
__global__ void __launch_bounds__(256) prep_kernel(
    const float* __restrict__ stacks,
    const void*  __restrict__ thickness,
    const int*   __restrict__ mat_idx,
    const int*   __restrict__ sub_idx_p,
    const int*   __restrict__ eos_p,
    const int*   __restrict__ pad_p,
    const int*   __restrict__ msk_p)
{
    int bx  = blockIdx.x;
    int b   = bx >> 2, chunk = bx & 3;
    int tid = threadIdx.x;
    int wid = tid >> 5, lid = tid & 31;
    int s   = chunk * 8 + wid;
    int eos = eos_p ? eos_p[0] : 0;
    int pad = pad_p ? pad_p[0] : 1;
    int msk = msk_p ? msk_p[0] : 2;

    __shared__ int s_fl;
    if (tid == 0) s_fl = is_f64(thickness, 4, 4.5f, 210.f);
    __syncthreads();
    bool th64 = s_fl != 0;
    int  sub  = sub_idx_p[0];

    const float* sp = stacks + ((size_t)(b * Sn + s)) * Vn;
    float q[8] = {0.f,0.f,0.f,0.f,0.f,0.f,0.f,0.f};
    float z = 0.f, ts = 0.f;
    #pragma unroll
    for (int j = 0; j < 16; ++j) {
        int v = lid + 32 * j;
        float p = sp[v];
        if (v == eos || v == pad || v == msk) p = 0.f;
        z  += p;
        ts += p * ldF(thickness, v, th64);
        int mv = mat_idx[v];
        #pragma unroll
        for (int m = 0; m < 8; ++m) q[m] += (mv == m) ? p : 0.f;
    }
    #pragma unroll
    for (int off = 16; off; off >>= 1) {
        z  += __shfl_down_sync(0xffffffffu, z,  off);
        ts += __shfl_down_sync(0xffffffffu, ts, off);
        #pragma unroll
        for (int m = 0; m < 8; ++m) q[m] += __shfl_down_sync(0xffffffffu, q[m], off);
    }
    if (lid == 0) {
        int bs = b * Sn + s;
        if (z > 0.f) {
            float inv = 1.0f / fmaxf(z, 1e-8f);
            ts *= inv;
            #pragma unroll
            for (int m = 0; m < 8; ++m) g_q[bs * 8 + m] = q[m] * inv;
        } else {
            ts = 0.f;
            #pragma unroll
            for (int m = 0; m < 8; ++m) g_q[bs * 8 + m] = (m == sub) ? 1.f : 0.f;
        }
        g_traw[bs] = ts;
        float pe = sp[eos];
        g_pe[bs] = fminf(fmaxf(pe, 0.f), 1.f);
    }
}

// ---------------------------------------------------------------------------
// Kernel 2: TMM. Asymmetric chain split:
//  half0 (tid<64): FORWARD rows of M0 (entry + layers 0..N0-1), 13 steps, 4-cplx state
//  half1 (tid>=64): REVERSE column col1(M1) (layers N0..31 + exit), 19 steps, 2-cplx state
// Combine: (At,Ct) = M0_rows . V. One thread = f32x2 pair (w, w+1024). grid (16,64).
// H-transform add/subs issued as scalar FADD pairs (alu pipe) to relieve FMA pipe.
// ---------------------------------------------------------------------------
__global__ void __launch_bounds__(128) tmm_kernel(
    const void* __restrict__ wl,
    const float* __restrict__ theta,
    const void* __restrict__ nk_real,
    const void* __restrict__ nk_imag,
    float* __restrict__ out)
{
    int b    = blockIdx.y;
    int tid  = threadIdx.x;
    int half = tid >> 6;                        // warp-uniform
    int l64  = tid & 63;
    int base = blockIdx.x * 64 + l64;           // 0..1023
    int w0   = base, w1 = base + 1024;

    __shared__ int    s_fl;
    __shared__ float2 s_qp[Sn * 8];             // q duplicated (lo=hi) for LDS.64
    __shared__ float  s_t[Sn];                  // survival-adjusted thickness
    __shared__ u64t   s_m[64][5];               // half1: V1r V1i V2r V2i KK1

    if (tid == 0) {
        int fl = 0;
        fl |= is_f64(nk_real, 0, 1.2f,    4.3f)  ? 1 : 0;
        fl |= is_f64(nk_imag, 0, -0.001f, 0.55f) ? 2 : 0;
        fl |= is_f64(wl,      0, 395.f,   1105.f)? 8 : 0;
        s_fl = fl;
    }
    if (tid < 32) {                              // survival scan (warp 0)
        float traw = g_traw[b * Sn + tid];
        float x = (tid == 0) ? 1.f : (1.f - g_pe[b * Sn + tid - 1] + 1e-12f);
        #pragma unroll
        for (int off = 1; off < 32; off <<= 1) {
            float y = __shfl_up_sync(0xffffffffu, x, off);
            if (tid >= off) x *= y;
        }
        s_t[tid] = traw * x;
    }
    for (int i = tid; i < Sn * 8; i += 128) {
        float v = g_q[b * Sn * 8 + i];
        s_qp[i] = make_float2(v, v);
    }
    __syncthreads();

    int fl = s_fl;
    bool nkr64 = (fl & 1), nki64 = (fl & 2), wl64 = (fl & 8);

    float th0 = theta[0];
    float s0  = sinf(th0);
    float s02 = s0 * s0;
    float f0r = (s02 > 0.f) ? sqrtf(fmaxf(1.f - s02, 0.f)) : 1.f;
    u64t  f0r2 = pks(f0r);

    float lm0 = ldF(wl, w0, wl64), lm1 = ldF(wl, w1, wl64);
    u64t cw2 = pk(6.283185307179586f / lm0, 6.283185307179586f / lm1);

    u64t nkr2[8], nki2[8];
    #pragma unroll
    for (int m = 0; m < 8; ++m) {
        nkr2[m] = pk(ldF(nk_real, m * Wn + w0, nkr64), ldF(nk_real, m * Wn + w1, nkr64));
        nki2[m] = pk(ldF(nk_imag, m * Wn + w0, nki64), ldF(nk_imag, m * Wn + w1, nki64));
    }

    const u64t Q25 = pks(0.25f);

    auto layern = [&](int s, u64t& nr2, u64t& ni2) {
        const float2* qp = s_qp + s * 8;
        u64t q0 = *(const u64t*)&qp[0];
        nr2 = mul2(q0, nkr2[0]);
        ni2 = mul2(q0, nki2[0]);
        #pragma unroll
        for (int m = 1; m < 8; ++m) {
            u64t qm = *(const u64t*)&qp[m];
            nr2 = fma2(qm, nkr2[m], nr2);
            ni2 = fma2(qm, nki2[m], ni2);
        }
        if (s02 > 0.f) {                        // general theta (not taken: th0=0)
            float nr[2], ni[2];
            upk(nr2, nr[0], nr[1]); upk(ni2, ni[0], ni[1]);
            #pragma unroll
            for (int l = 0; l < 2; ++l) {
                float zr = nr[l] * nr[l] - ni[l] * ni[l] - s02;
                float zi = 2.f * nr[l] * ni[l];
                float ll = sqrtf(zr * zr + zi * zi);
                float wr = sqrtf(fmaxf(0.5f * (ll + zr), 0.f));
                float wi = sqrtf(fmaxf(0.5f * (ll - zr), 0.f));
                if (zi < 0.f) wi = -wi;
                nr[l] = wr; ni[l] = wi;
            }
            nr2 = pk(nr[0], nr[1]); ni2 = pk(ni[0], ni[1]);
        }
    };

    // phase factors for the CURRENT step (pipelined one step ahead)
    u64t p_cs4, p_sn4, p_qr, p_qi, p_kkf;
    auto phase = [&](u64t fr2, u64t fi2, float tt,
                     u64t& o_cs4, u64t& o_sn4, u64t& o_qr, u64t& o_qi, u64t& o_kkf) {
        u64t ct2 = mul2(cw2, pks(tt));
        u64t dr2 = mul2(ct2, fr2);
        u64t di2 = mul2(ct2, fi2);
        float dr0, dr1, di0, di1;
        upk(dr2, dr0, dr1); upk(di2, di0, di1);
        di0 = fminf(di0, 35.f); di1 = fminf(di1, 35.f);   // DELTA_IMAG_CLAMP
        float sn0, cs0, sn1, cs1;
        __sincosf(dr0, &sn0, &cs0);
        __sincosf(dr1, &sn1, &cs1);
        float E0 = __expf(-2.f * di0), E1 = __expf(-2.f * di1);
        u64t cs2p = pk(cs0, cs1), sn2p = pk(sn0, sn1);
        u64t Eq2  = mul2(pk(E0, E1), Q25);
        o_cs4 = mul2(cs2p, Q25);
        o_sn4 = mul2(sn2p, Q25);
        o_qr  = mul2(Eq2, cs2p);
        o_qi  = mul2(Eq2, sn2p);
        u64t mag2 = fma2(fi2, fi2, mul2(fr2, fr2));
        o_kkf = mul2(mag2, Eq2);                 // |f1|^2 * 0.25 * e^{-2di}
    };

    u64t KK2;
    u64t f1r2, f1i2;

    size_t ob = (size_t)b * (3 * Wn);

    if (half == 1) {
        // ---------------- half 1: reverse column accumulation ----------------
        layern(Sn - 1, f1r2, f1i2);              // layer 31
        u64t f2r2 = f0r2, f2i2 = 0ULL;           // exit boundary (n=1)
        phase(f1r2, f1i2, s_t[Sn - 1], p_cs4, p_sn4, p_qr, p_qi, p_kkf);

        u64t V1r = pks(1.f), V1i = 0ULL, V2r = 0ULL, V2i = 0ULL;
        KK2 = pks(1.f);

        auto cstep = [&](u64t fbr, u64t fbi) {   // f1 = current layer, fb = next(f2)
            u64t Gr = adds2(V1r, V2r), Gi = adds2(V1i, V2i);
            u64t Hr = subs2(V1r, V2r), Hi = subs2(V1i, V2i);
            u64t nf1i = neg2(f1i2), nfbi = neg2(fbi);
            u64t T1r = fma2(nf1i, Gi, mul2(f1r2, Gr));
            u64t T1i = fma2(f1i2, Gr, mul2(f1r2, Gi));
            u64t T2r = fma2(nfbi, Hi, mul2(fbr, Hr));
            u64t T2i = fma2(fbi,  Hr, mul2(fbr, Hi));
            u64t W1r = adds2(T1r, T2r), W1i = adds2(T1i, T2i);
            u64t W2r = subs2(T1r, T2r), W2i = subs2(T1i, T2i);
            // V1 = (1/4)cis(-dr) * W1
            V1r = fma2(p_sn4, W1i, mul2(p_cs4, W1r));
            V1i = fma2(neg2(p_sn4), W1r, mul2(p_cs4, W1i));
            // V2 = (1/4)Qhat * W2
            V2r = fma2(neg2(p_qi), W2i, mul2(p_qr, W2r));
            V2i = fma2(p_qi, W2r, mul2(p_qr, W2i));
            KK2 = mul2(KK2, p_kkf);
        };

        // steps j = 31 .. 14 (pipelined), then final j = 13
        #pragma unroll 1
        for (int k = 0; k < Sn - 1 - N0; ++k) {  // 18 iterations
            int j = Sn - 1 - k;                  // 31..14
            u64t fprer, fprei;                   // layer j-1
            layern(j - 1, fprer, fprei);
            u64t n_cs4, n_sn4, n_qr, n_qi, n_kkf;
            phase(fprer, fprei, s_t[j - 1], n_cs4, n_sn4, n_qr, n_qi, n_kkf);
            cstep(f2r2, f2i2);
            f2r2 = f1r2; f2i2 = f1i2;            // next step's f2 = this layer
            f1r2 = fprer; f1i2 = fprei;
            p_cs4 = n_cs4; p_sn4 = n_sn4; p_qr = n_qr; p_qi = n_qi; p_kkf = n_kkf;
        }
        cstep(f2r2, f2i2);                       // j = N0 = 13

        s_m[l64][0] = V1r; s_m[l64][1] = V1i;
        s_m[l64][2] = V2r; s_m[l64][3] = V2i;
        s_m[l64][4] = KK2;
        __syncthreads();
    } else {
        // ---------------- half 0: forward rows of M0 ----------------
        layern(0, f1r2, f1i2);
        u64t nf1i = neg2(f1i2);
        phase(f1r2, f1i2, s_t[0], p_cs4, p_sn4, p_qr, p_qi, p_kkf);

        const u64t HALF = pks(0.5f);
        u64t Ar2 = mul2(adds2(f0r2, f1r2), HALF);
        u64t Ai2 = mul2(f1i2, HALF);
        u64t Br2 = mul2(subs2(f0r2, f1r2), HALF);
        u64t Bi2 = neg2(Ai2);
        u64t Cr2 = Br2, Ci2 = Bi2, Dr2 = Ar2, Di2 = Ai2;
        KK2 = pks(f0r * f0r);

        auto step = [&](u64t f2r2, u64t f2i2) {
            u64t nsn4 = neg2(p_sn4), nqi = neg2(p_qi);
            u64t nf2i = neg2(f2i2);
            u64t ur = fma2(Ai2, p_sn4, mul2(Ar2, p_cs4));
            u64t ui = fma2(Ar2, nsn4,  mul2(Ai2, p_cs4));
            u64t vr = fma2(Bi2, nqi,   mul2(Br2, p_qr));
            u64t vi = fma2(Bi2, p_qr,  mul2(Br2, p_qi));
            u64t xr = fma2(Ci2, p_sn4, mul2(Cr2, p_cs4));
            u64t xi = fma2(Cr2, nsn4,  mul2(Ci2, p_cs4));
            u64t yr = fma2(Di2, nqi,   mul2(Dr2, p_qr));
            u64t yi = fma2(Di2, p_qr,  mul2(Dr2, p_qi));

            u64t Pr = adds2(ur, vr), Pi = adds2(ui, vi);
            u64t Mr = subs2(ur, vr), Mi = subs2(ui, vi);
            u64t Xr = adds2(xr, yr), Xi = adds2(xi, yi);
            u64t Yr = subs2(xr, yr), Yi = subs2(xi, yi);

            u64t T1r = fma2(Pi, nf1i, mul2(Pr, f1r2));
            u64t T1i = fma2(Pi, f1r2, mul2(Pr, f1i2));
            u64t T2r = fma2(Mi, nf2i, mul2(Mr, f2r2));
            u64t T2i = fma2(Mi, f2r2, mul2(Mr, f2i2));
            u64t U1r = fma2(Xi, nf1i, mul2(Xr, f1r2));
            u64t U1i = fma2(Xi, f1r2, mul2(Xr, f1i2));
            u64t U2r = fma2(Yi, nf2i, mul2(Yr, f2r2));
            u64t U2i = fma2(Yi, f2r2, mul2(Yr, f2i2));

            Ar2 = adds2(T1r, T2r);  Ai2 = adds2(T1i, T2i);
            Br2 = subs2(T1r, T2r);  Bi2 = subs2(T1i, T2i);
            Cr2 = adds2(U1r, U2r);  Ci2 = adds2(U1i, U2i);
            Dr2 = subs2(U1r, U2r);  Di2 = subs2(U1i, U2i);
            KK2 = mul2(KK2, p_kkf);
            f1r2 = f2r2; f1i2 = f2i2; nf1i = nf2i;
        };

        // steps s = 0 .. N0-2 (pipelined), then final s = N0-1 into layer N0
        #pragma unroll 1
        for (int k = 0; k < N0 - 1; ++k) {       // 12 iterations
            u64t f2r2, f2i2;
            layern(k + 1, f2r2, f2i2);
            u64t n_cs4, n_sn4, n_qr, n_qi, n_kkf;
            phase(f2r2, f2i2, s_t[k + 1], n_cs4, n_sn4, n_qr, n_qi, n_kkf);
            step(f2r2, f2i2);
            p_cs4 = n_cs4; p_sn4 = n_sn4; p_qr = n_qr; p_qi = n_qi; p_kkf = n_kkf;
        }
        {
            u64t f2r2, f2i2;
            layern(N0, f2r2, f2i2);
            step(f2r2, f2i2);                    // step N0-1, interface into layer N0
        }

        __syncthreads();

        u64t V1r = s_m[l64][0], V1i = s_m[l64][1];
        u64t V2r = s_m[l64][2], V2i = s_m[l64][3];
        u64t KK1 = s_m[l64][4];
        // (At, Ct) = M0_rows . V
        u64t Atr = fma2(Bi2, neg2(V2i), fma2(Br2, V2r, fma2(Ai2, neg2(V1i), mul2(Ar2, V1r))));
        u64t Ati = fma2(Bi2, V2r,       fma2(Br2, V2i, fma2(Ai2, V1r,       mul2(Ar2, V1i))));
        u64t Ctr = fma2(Di2, neg2(V2i), fma2(Dr2, V2r, fma2(Ci2, neg2(V1i), mul2(Cr2, V1r))));
        u64t Cti = fma2(Di2, V2r,       fma2(Dr2, V2i, fma2(Ci2, V1r,       mul2(Cr2, V1i))));
        u64t KKt = mul2(KK2, KK1);

        float Ar[2], Ai[2], Cr[2], Ci[2], KK[2];
        upk(Atr, Ar[0], Ar[1]); upk(Ati, Ai[0], Ai[1]);
        upk(Ctr, Cr[0], Cr[1]); upk(Cti, Ci[0], Ci[1]);
        upk(KKt, KK[0], KK[1]);

        #pragma unroll
        for (int l = 0; l < 2; ++l) {
            float mm  = fabsf(Ar[l]) + fabsf(Ai[l]);
            float inv = 1.0f / mm;
            float ar = Ar[l] * inv, ai = Ai[l] * inv;
            float cr = Cr[l] * inv, ci = Ci[l] * inv;
            float invda = 1.0f / (ar * ar + ai * ai);
            float R = (cr * cr + ci * ci) * invda;
            float T = (KK[l] * inv) * inv * invda;
            R = isfinite(R) ? R : 0.f;  R = fminf(fmaxf(R, 0.f), 1.f);
            T = isfinite(T) ? T : 0.f;  T = fminf(fmaxf(T, 0.f), 1.f);
            float Aab = 1.f - R - T;
            Aab = isfinite(Aab) ? Aab : 0.f;  Aab = fminf(fmaxf(Aab, 0.f), 1.f);
            int w = (l == 0) ? w0 : w1;
            out[ob + w]          = R;
            out[ob + Wn + w]     = Aab;
            out[ob + 2 * Wn + w] = T;
        }
    }
}

// ---------------------------------------------------------------------------
extern "C" void kernel_launch(void* const* d_in, const int* in_sizes, int n_in,
                              void* d_out, int out_size)
{
    const float* stacks    = (const float*)d_in[0];
    const void*  wl        = d_in[1];
    const float* theta     = (const float*)d_in[2];
    const void*  nk_real   = d_in[3];
    const void*  nk_imag   = d_in[4];
    const void*  thickness = d_in[5];
    const int*   mat_idx   = (const int*)d_in[6];
    const int*   sub_idx   = (const int*)d_in[7];
    const int*   eos_p     = (n_in > 8)  ? (const int*)d_in[8]  : nullptr;
    const int*   pad_p     = (n_in > 9)  ? (const int*)d_in[9]  : nullptr;
    const int*   msk_p     = (n_in > 10) ? (const int*)d_in[10] : nullptr;
    float* out = (float*)d_out;

    prep_kernel<<<Bn * 4, 256>>>(stacks, thickness, mat_idx, sub_idx,
                                 eos_p, pad_p, msk_p);
    tmm_kernel<<<dim3(16, Bn), 128>>>(wl, theta, nk_real, nk_imag, out);
}

// round 16
// speedup vs baseline: 1.6323x; 1.6323x over previous
#include <cuda_runtime.h>
#include <math.h>

#define Bn 64
#define Sn 32
#define Vn 512
#define Wn 2048

typedef unsigned long long u64t;

// Scratch (no allocations allowed)
__device__ __align__(16) float g_q[Bn * Sn * 8];  // [b][s][m] material weight
__device__ float g_traw[Bn * Sn];                 // thickness before survival
__device__ float g_pe[Bn * Sn];                   // clipped eos prob

__device__ __forceinline__ float ldF(const void* p, int i, bool f64) {
    return f64 ? (float)((const double*)p)[i] : ((const float*)p)[i];
}

// Structural f64 detection: if buffer is f64, even-index float words are raw
// mantissa bits -> essentially never all within the known value range.
__device__ __forceinline__ int is_f64(const void* p, int start, float lo, float hi) {
    const float* f = (const float*)p;
    for (int i = 0; i < 16; ++i) {
        float v = f[start + 2 * i];
        if (!(v >= lo && v <= hi)) return 1;
    }
    return 0;
}

// ---- packed f32x2 helpers (FFMA2 path: only reachable via PTX) ----
__device__ __forceinline__ u64t pk(float lo, float hi) {
    u64t r; asm("mov.b64 %0, {%1,%2};" : "=l"(r) : "f"(lo), "f"(hi)); return r;
}
__device__ __forceinline__ u64t pks(float x) { return pk(x, x); }
__device__ __forceinline__ void upk(u64t a, float& lo, float& hi) {
    asm("mov.b64 {%0,%1}, %2;" : "=f"(lo), "=f"(hi) : "l"(a));
}
__device__ __forceinline__ u64t mul2(u64t a, u64t b) {
    u64t r; asm("mul.rn.f32x2 %0,%1,%2;" : "=l"(r) : "l"(a), "l"(b)); return r;
}
__device__ __forceinline__ u64t add2(u64t a, u64t b) {
    u64t r; asm("add.rn.f32x2 %0,%1,%2;" : "=l"(r) : "l"(a), "l"(b)); return r;
}
__device__ __forceinline__ u64t fma2(u64t a, u64t b, u64t c) {
    u64t r; asm("fma.rn.f32x2 %0,%1,%2,%3;" : "=l"(r) : "l"(a), "l"(b), "l"(c)); return r;
}
__device__ __forceinline__ u64t neg2(u64t a) { return a ^ 0x8000000080000000ULL; }

// ---------------------------------------------------------------------------
// Kernel 1: prep. grid = Bn*4 blocks, 256 threads; ONE WARP per (b,s).
// Writes g_q, g_traw (pre-survival thickness), g_pe. Survival moved to tmm.
// ---------------------------------------------------------------------------
__global__ void __launch_bounds__(256) prep_kernel(
    const float* __restrict__ stacks,
    const void*  __restrict__ thickness,
    const int*   __restrict__ mat_idx,
    const int*   __restrict__ sub_idx_p,
    const int*   __restrict__ eos_p,
    const int*   __restrict__ pad_p,
    const int*   __restrict__ msk_p)
{
    int bx  = blockIdx.x;
    int b   = bx >> 2, chunk = bx & 3;
    int tid = threadIdx.x;
    int wid = tid >> 5, lid = tid & 31;
    int s   = chunk * 8 + wid;
    int eos = eos_p ? eos_p[0] : 0;
    int pad = pad_p ? pad_p[0] : 1;
    int msk = msk_p ? msk_p[0] : 2;

    __shared__ int s_fl;
    if (tid == 0) s_fl = is_f64(thickness, 4, 4.5f, 210.f);  // skip zeroed idx 0..2
    __syncthreads();
    bool th64 = s_fl != 0;
    int  sub  = sub_idx_p[0];

    const float* sp = stacks + ((size_t)(b * Sn + s)) * Vn;
    float q[8] = {0.f,0.f,0.f,0.f,0.f,0.f,0.f,0.f};
    float z = 0.f, ts = 0.f;
    #pragma unroll
    for (int j = 0; j < 16; ++j) {
        int v = lid + 32 * j;
        float p = sp[v];
        if (v == eos || v == pad || v == msk) p = 0.f;
        z  += p;
        ts += p * ldF(thickness, v, th64);
        int mv = mat_idx[v];
        #pragma unroll
        for (int m = 0; m < 8; ++m) q[m] += (mv == m) ? p : 0.f;
    }
    #pragma unroll
    for (int off = 16; off; off >>= 1) {
        z  += __shfl_down_sync(0xffffffffu, z,  off);
        ts += __shfl_down_sync(0xffffffffu, ts, off);
        #pragma unroll
        for (int m = 0; m < 8; ++m) q[m] += __shfl_down_sync(0xffffffffu, q[m], off);
    }
    if (lid == 0) {
        int bs = b * Sn + s;
        if (z > 0.f) {
            float inv = 1.0f / fmaxf(z, 1e-8f);
            ts *= inv;
            #pragma unroll
            for (int m = 0; m < 8; ++m) g_q[bs * 8 + m] = q[m] * inv;
        } else {
            ts = 0.f;
            #pragma unroll
            for (int m = 0; m < 8; ++m) g_q[bs * 8 + m] = (m == sub) ? 1.f : 0.f;
        }
        g_traw[bs] = ts;
        float pe = sp[eos];
        g_pe[bs] = fminf(fmaxf(pe, 0.f), 1.f);
    }
}

// ---------------------------------------------------------------------------
// Kernel 2: TMM, chain split in two 16-step halves (matrix associativity),
// P/M-form step + one-step-ahead MUFU phase pipelining.
// Launched with PDL: the prologue up to cudaGridDependencySynchronize() is
// independent of prep's output and overlaps prep's tail + launch latency.
// ---------------------------------------------------------------------------
__global__ void __launch_bounds__(128) tmm_kernel(
    const void* __restrict__ wl,
    const float* __restrict__ theta,
    const void* __restrict__ nk_real,
    const void* __restrict__ nk_imag,
    float* __restrict__ out)
{
    int b    = blockIdx.y;
    int tid  = threadIdx.x;
    int half = tid >> 6;                        // warp-uniform
    int l64  = tid & 63;
    int base = blockIdx.x * 64 + l64;           // 0..1023
    int w0   = base, w1 = base + 1024;

    __shared__ int    s_fl;
    __shared__ float2 s_qp[Sn * 8];             // q duplicated (lo=hi) for LDS.64
    __shared__ float  s_t[Sn];                  // survival-adjusted thickness
    __shared__ u64t   s_m[64][5];               // half1: A1r A1i C1r C1i KK1

    // ---- prep-independent prologue (overlaps prep via PDL) ----
    if (tid == 0) {
        int fl = 0;
        fl |= is_f64(nk_real, 0, 1.2f,    4.3f)  ? 1 : 0;
        fl |= is_f64(nk_imag, 0, -0.001f, 0.55f) ? 2 : 0;
        fl |= is_f64(wl,      0, 395.f,   1105.f)? 8 : 0;
        s_fl = fl;
    }
    __syncthreads();
    int fl = s_fl;
    bool nkr64 = (fl & 1), nki64 = (fl & 2), wl64 = (fl & 8);

    float th0 = theta[0];
    float s0  = sinf(th0);
    float s02 = s0 * s0;
    float f0r = (s02 > 0.f) ? sqrtf(fmaxf(1.f - s02, 0.f)) : 1.f;
    u64t  f0r2 = pks(f0r);

    float lm0 = ldF(wl, w0, wl64), lm1 = ldF(wl, w1, wl64);
    u64t cw2 = pk(6.283185307179586f / lm0, 6.283185307179586f / lm1);

    u64t nkr2[8], nki2[8];
    #pragma unroll
    for (int m = 0; m < 8; ++m) {
        nkr2[m] = pk(ldF(nk_real, m * Wn + w0, nkr64), ldF(nk_real, m * Wn + w1, nkr64));
        nki2[m] = pk(ldF(nk_imag, m * Wn + w0, nki64), ldF(nk_imag, m * Wn + w1, nki64));
    }

    // ---- wait for prep's global writes, then consume them ----
#if __CUDA_ARCH__ >= 900
    cudaGridDependencySynchronize();
#endif

    if (tid < 32) {                              // survival scan (warp 0)
        float traw = g_traw[b * Sn + tid];
        float x = (tid == 0) ? 1.f : (1.f - g_pe[b * Sn + tid - 1] + 1e-12f);
        #pragma unroll
        for (int off = 1; off < 32; off <<= 1) { // inclusive product scan
            float y = __shfl_up_sync(0xffffffffu, x, off);
            if (tid >= off) x *= y;
        }
        s_t[tid] = traw * x;                     // active_s = prod_{k<s}
    }
    for (int i = tid; i < Sn * 8; i += 128) {
        float v = g_q[b * Sn * 8 + i];
        s_qp[i] = make_float2(v, v);
    }
    __syncthreads();

    const u64t Q25 = pks(0.25f);

    auto layern = [&](int s, u64t& nr2, u64t& ni2) {
        const float2* qp = s_qp + s * 8;
        u64t q0 = *(const u64t*)&qp[0];
        nr2 = mul2(q0, nkr2[0]);
        ni2 = mul2(q0, nki2[0]);
        #pragma unroll
        for (int m = 1; m < 8; ++m) {
            u64t qm = *(const u64t*)&qp[m];
            nr2 = fma2(qm, nkr2[m], nr2);
            ni2 = fma2(qm, nki2[m], ni2);
        }
        if (s02 > 0.f) {                        // general theta (not taken: th0=0)
            float nr[2], ni[2];
            upk(nr2, nr[0], nr[1]); upk(ni2, ni[0], ni[1]);
            #pragma unroll
            for (int l = 0; l < 2; ++l) {
                float zr = nr[l] * nr[l] - ni[l] * ni[l] - s02;
                float zi = 2.f * nr[l] * ni[l];
                float ll = sqrtf(zr * zr + zi * zi);
                float wr = sqrtf(fmaxf(0.5f * (ll + zr), 0.f));
                float wi = sqrtf(fmaxf(0.5f * (ll - zr), 0.f));
                if (zi < 0.f) wi = -wi;
                nr[l] = wr; ni[l] = wi;
            }
            nr2 = pk(nr[0], nr[1]); ni2 = pk(ni[0], ni[1]);
        }
    };

    int sbeg = half * 16;                       // 0 or 16
    u64t f1r2, f1i2;
    layern(sbeg, f1r2, f1i2);
    u64t nf1i = neg2(f1i2);

    // state
    u64t Ar2, Ai2, Br2, Bi2, Cr2, Ci2, Dr2, Di2, KK2;
    if (half == 0) {                            // true entry-interface init
        const u64t HALF = pks(0.5f);
        Ar2 = mul2(add2(f0r2, f1r2), HALF);
        Ai2 = mul2(f1i2, HALF);
        Br2 = mul2(add2(f0r2, neg2(f1r2)), HALF);
        Bi2 = neg2(Ai2);
        Cr2 = Br2; Ci2 = Bi2; Dr2 = Ar2; Di2 = Ai2;
        KK2 = pks(f0r * f0r);
    } else {                                    // identity, unit scale
        Ar2 = pks(1.f); Ai2 = 0ULL;
        Br2 = 0ULL;     Bi2 = 0ULL;
        Cr2 = 0ULL;     Ci2 = 0ULL;
        Dr2 = pks(1.f); Di2 = 0ULL;
        KK2 = pks(1.f);
    }

    // phase factors for the CURRENT step (computed one step ahead in the loop)
    u64t p_cs4, p_sn4, p_qr, p_qi, p_kkf;
    auto phase = [&](u64t fr2, u64t fi2, float tt,
                     u64t& o_cs4, u64t& o_sn4, u64t& o_qr, u64t& o_qi, u64t& o_kkf) {
        u64t ct2 = mul2(cw2, pks(tt));
        u64t dr2 = mul2(ct2, fr2);
        u64t di2 = mul2(ct2, fi2);
        float dr0, dr1, di0, di1;
        upk(dr2, dr0, dr1); upk(di2, di0, di1);
        di0 = fminf(di0, 35.f); di1 = fminf(di1, 35.f);   // DELTA_IMAG_CLAMP
        float sn0, cs0, sn1, cs1;
        __sincosf(dr0, &sn0, &cs0);
        __sincosf(dr1, &sn1, &cs1);
        float E0 = __expf(-2.f * di0), E1 = __expf(-2.f * di1);
        u64t cs2p = pk(cs0, cs1), sn2p = pk(sn0, sn1);
        u64t Eq2  = mul2(pk(E0, E1), Q25);
        o_cs4 = mul2(cs2p, Q25);
        o_sn4 = mul2(sn2p, Q25);
        o_qr  = mul2(Eq2, cs2p);
        o_qi  = mul2(Eq2, sn2p);
        u64t mag2 = fma2(fi2, fi2, mul2(fr2, fr2));
        o_kkf = mul2(mag2, Eq2);                 // |f1|^2 * 0.25 * e^{-2di}
    };
    phase(f1r2, f1i2, s_t[sbeg], p_cs4, p_sn4, p_qr, p_qi, p_kkf);

    // P/M-form step: A' = P*f1 + M*f2, B' = P*f1 - M*f2 (P=u+v, M=u-v)
    auto step = [&](u64t f2r2, u64t f2i2) {
        u64t nsn4 = neg2(p_sn4), nqi = neg2(p_qi);
        u64t nf2i = neg2(f2i2);
        u64t ur = fma2(Ai2, p_sn4, mul2(Ar2, p_cs4));
        u64t ui = fma2(Ar2, nsn4,  mul2(Ai2, p_cs4));
        u64t vr = fma2(Bi2, nqi,   mul2(Br2, p_qr));
        u64t vi = fma2(Bi2, p_qr,  mul2(Br2, p_qi));
        u64t xr = fma2(Ci2, p_sn4, mul2(Cr2, p_cs4));
        u64t xi = fma2(Cr2, nsn4,  mul2(Ci2, p_cs4));
        u64t yr = fma2(Di2, nqi,   mul2(Dr2, p_qr));
        u64t yi = fma2(Di2, p_qr,  mul2(Dr2, p_qi));

        u64t Pr = add2(ur, vr),        Pi = add2(ui, vi);
        u64t Mr = add2(ur, neg2(vr)),  Mi = add2(ui, neg2(vi));
        u64t Xr = add2(xr, yr),        Xi = add2(xi, yi);
        u64t Yr = add2(xr, neg2(yr)),  Yi = add2(xi, neg2(yi));

        u64t T1r = fma2(Pi, nf1i, mul2(Pr, f1r2));
        u64t T1i = fma2(Pi, f1r2, mul2(Pr, f1i2));
        u64t T2r = fma2(Mi, nf2i, mul2(Mr, f2r2));
        u64t T2i = fma2(Mi, f2r2, mul2(Mr, f2i2));
        u64t U1r = fma2(Xi, nf1i, mul2(Xr, f1r2));
        u64t U1i = fma2(Xi, f1r2, mul2(Xr, f1i2));
        u64t U2r = fma2(Yi, nf2i, mul2(Yr, f2r2));
        u64t U2i = fma2(Yi, f2r2, mul2(Yr, f2i2));

        Ar2 = add2(T1r, T2r);        Ai2 = add2(T1i, T2i);
        Br2 = add2(T1r, neg2(T2r));  Bi2 = add2(T1i, neg2(T2i));
        Cr2 = add2(U1r, U2r);        Ci2 = add2(U1i, U2i);
        Dr2 = add2(U1r, neg2(U2r));  Di2 = add2(U1i, neg2(U2i));
        KK2 = mul2(KK2, p_kkf);
        f1r2 = f2r2; f1i2 = f2i2; nf1i = nf2i;
    };

    // 15 pipelined steps: compute next layer + next phase BEFORE this step's
    // matrix update so MUFU latency hides under the FFMA2 burst.
    #pragma unroll 1
    for (int k = 0; k < 15; ++k) {
        int s = sbeg + k;
        u64t f2r2, f2i2;
        layern(s + 1, f2r2, f2i2);
        u64t n_cs4, n_sn4, n_qr, n_qi, n_kkf;
        phase(f2r2, f2i2, s_t[s + 1], n_cs4, n_sn4, n_qr, n_qi, n_kkf);
        step(f2r2, f2i2);
        p_cs4 = n_cs4; p_sn4 = n_sn4; p_qr = n_qr; p_qi = n_qi; p_kkf = n_kkf;
    }
    if (half == 0) {                            // final: interface to layer 16
        u64t f2r2, f2i2;
        layern(16, f2r2, f2i2);
        step(f2r2, f2i2);
    } else {                                    // final: exit boundary (n=1)
        step(f0r2, 0ULL);
    }

    if (half == 1) {                            // publish first column + KK
        s_m[l64][0] = Ar2; s_m[l64][1] = Ai2;
        s_m[l64][2] = Cr2; s_m[l64][3] = Ci2;
        s_m[l64][4] = KK2;
    }
    __syncthreads();

    if (half == 0) {
        u64t A1r = s_m[l64][0], A1i = s_m[l64][1];
        u64t C1r = s_m[l64][2], C1i = s_m[l64][3];
        u64t KK1 = s_m[l64][4];
        // M_tot col1 = M0 * (A1, C1)^T
        u64t Atr = fma2(Bi2, neg2(C1i), fma2(Br2, C1r, fma2(Ai2, neg2(A1i), mul2(Ar2, A1r))));
        u64t Ati = fma2(Bi2, C1r,       fma2(Br2, C1i, fma2(Ai2, A1r,       mul2(Ar2, A1i))));
        u64t Ctr = fma2(Di2, neg2(C1i), fma2(Dr2, C1r, fma2(Ci2, neg2(A1i), mul2(Cr2, A1r))));
        u64t Cti = fma2(Di2, C1r,       fma2(Dr2, C1i, fma2(Ci2, A1r,       mul2(Cr2, A1i))));
        u64t KKt = mul2(KK2, KK1);

        float Ar[2], Ai[2], Cr[2], Ci[2], KK[2];
        upk(Atr, Ar[0], Ar[1]); upk(Ati, Ai[0], Ai[1]);
        upk(Ctr, Cr[0], Cr[1]); upk(Cti, Ci[0], Ci[1]);
        upk(KKt, KK[0], KK[1]);

        size_t ob = (size_t)b * (3 * Wn);
        #pragma unroll
        for (int l = 0; l < 2; ++l) {
            float mm  = fabsf(Ar[l]) + fabsf(Ai[l]);
            float inv = 1.0f / mm;
            float ar = Ar[l] * inv, ai = Ai[l] * inv;
            float cr = Cr[l] * inv, ci = Ci[l] * inv;
            float invda = 1.0f / (ar * ar + ai * ai);
            float R = (cr * cr + ci * ci) * invda;
            float T = (KK[l] * inv) * inv * invda;
            R = isfinite(R) ? R : 0.f;  R = fminf(fmaxf(R, 0.f), 1.f);
            T = isfinite(T) ? T : 0.f;  T = fminf(fmaxf(T, 0.f), 1.f);
            float Aab = 1.f - R - T;
            Aab = isfinite(Aab) ? Aab : 0.f;  Aab = fminf(fmaxf(Aab, 0.f), 1.f);
            int w = (l == 0) ? w0 : w1;
            out[ob + w]          = R;
            out[ob + Wn + w]     = Aab;
            out[ob + 2 * Wn + w] = T;
        }
    }
}

// ---------------------------------------------------------------------------
extern "C" void kernel_launch(void* const* d_in, const int* in_sizes, int n_in,
                              void* d_out, int out_size)
{
    const float* stacks    = (const float*)d_in[0];
    const void*  wl        = d_in[1];
    const float* theta     = (const float*)d_in[2];
    const void*  nk_real   = d_in[3];
    const void*  nk_imag   = d_in[4];
    const void*  thickness = d_in[5];
    const int*   mat_idx   = (const int*)d_in[6];
    const int*   sub_idx   = (const int*)d_in[7];
    const int*   eos_p     = (n_in > 8)  ? (const int*)d_in[8]  : nullptr;
    const int*   pad_p     = (n_in > 9)  ? (const int*)d_in[9]  : nullptr;
    const int*   msk_p     = (n_in > 10) ? (const int*)d_in[10] : nullptr;
    float* out = (float*)d_out;

    prep_kernel<<<Bn * 4, 256>>>(stacks, thickness, mat_idx, sub_idx,
                                 eos_p, pad_p, msk_p);

    // PDL launch: tmm may begin its prep-independent prologue while prep
    // drains; cudaGridDependencySynchronize() in the kernel orders the rest.
    cudaLaunchConfig_t cfg = {};
    cfg.gridDim  = dim3(16, Bn);
    cfg.blockDim = dim3(128);
    cfg.dynamicSmemBytes = 0;
    cfg.stream = 0;
    cudaLaunchAttribute attr[1];
    attr[0].id = cudaLaunchAttributeProgrammaticStreamSerialization;
    attr[0].val.programmaticStreamSerializationAllowed = 1;
    cfg.attrs = attr;
    cfg.numAttrs = 1;
    cudaError_t e = cudaLaunchKernelEx(&cfg, tmm_kernel,
                                       wl, theta,
                                       (const void*)nk_real, (const void*)nk_imag,
                                       out);
    if (e != cudaSuccess) {
        // Fallback: plain launch (no PDL) keeps correctness.
        tmm_kernel<<<dim3(16, Bn), 128>>>(wl, theta, nk_real, nk_imag, out);
    }
}